// round 15
// baseline (speedup 1.0000x reference)
#include <cuda_runtime.h>
#include <cuda_fp16.h>
#include <cstdint>

typedef unsigned long long ull;
typedef unsigned int u32;

#define NN    4096
#define BB    8
#define TT    12
#define BT    96
#define FOUT  12
#define HIDD  64
#define ROWS  128          // M tile
#define KC    32           // K chunk
#define SPLITK 8
#define KPER  (NN/SPLITK)  // 512
#define NITS  (KPER/KC)    // 16
#define RTILES (3*NN/ROWS) // 96
#define GSTRIDE 776        // gws row stride (768 + 8 pad: kills 4-way t-bank conflict)

#define CN (3*BB*TT*NN)    // 1,179,648

// stage layout in u32 units (pitch 20 u32 per row -> conflict-free LDS/LDSM)
#define U_AH 0
#define U_BH (128*20)                 // 2560
#define ST_U32 (128*20 + 96*20)       // 4480
#define ST_BYTES (ST_U32*4)           // 17920
#define SMEM_TOTAL (2*ST_BYTES)       // 35840

__device__ float g_part[SPLITK * CN];          // 37.7 MB partial planes
__device__ float g_C[CN];                      // reduced C, [k][b][t][n]
__device__ __align__(16) u32 g_xhi[BT*NN/2];   // x fp16 pairs

// ---------------------------------------------------------------- helpers
__device__ __forceinline__ u32 smem_u32(const void* p){
    u32 a; asm("{ .reg .u64 t; cvta.to.shared.u64 t, %1; cvt.u32.u64 %0, t; }"
               : "=r"(a) : "l"(p));
    return a;
}
__device__ __forceinline__ void cpasync16(u32 dst, const void* src){
    asm volatile("cp.async.cg.shared.global [%0], [%1], 16;"
                 :: "r"(dst), "l"(src) : "memory");
}
__device__ __forceinline__ void cp_commit(){
    asm volatile("cp.async.commit_group;" ::: "memory");
}
__device__ __forceinline__ void cp_wait0(){
    asm volatile("cp.async.wait_group 0;" ::: "memory");
}
__device__ __forceinline__ void ldsm4(u32* r, u32 addr){
    asm volatile("ldmatrix.sync.aligned.m8n8.x4.shared.b16 {%0,%1,%2,%3}, [%4];"
                 : "=r"(r[0]), "=r"(r[1]), "=r"(r[2]), "=r"(r[3]) : "r"(addr));
}
// pack two floats to one fp16x2 (rn)
__device__ __forceinline__ u32 pack_f16(float f0, float f1){
    u32 r; asm("cvt.rn.f16x2.f32 %0, %1, %2;" : "=r"(r) : "f"(f1), "f"(f0));
    return r;
}
__device__ __forceinline__ void mma16816(float* c, const u32* a, const u32* b){
    asm volatile(
      "mma.sync.aligned.m16n8k16.row.col.f32.f16.f16.f32 "
      "{%0,%1,%2,%3}, {%4,%5,%6,%7}, {%8,%9}, {%0,%1,%2,%3};"
      : "+f"(c[0]), "+f"(c[1]), "+f"(c[2]), "+f"(c[3])
      : "r"(a[0]), "r"(a[1]), "r"(a[2]), "r"(a[3]), "r"(b[0]), "r"(b[1]));
}
__device__ __forceinline__ ull f2dup(float f){
    ull r; asm("mov.b64 %0, {%1, %1};" : "=l"(r) : "f"(f)); return r;
}
__device__ __forceinline__ void ffma2(ull &d, ull a, ull b){
    asm("fma.rn.f32x2 %0, %1, %2, %3;" : "=l"(d) : "l"(a), "l"(b), "l"(d));
}

// ---------------------------------------------------------------- split x
__global__ __launch_bounds__(256) void split_x(const float* __restrict__ x){
    int i = blockIdx.x*256 + threadIdx.x;        // group of 4 pairs
    const float4* xp = reinterpret_cast<const float4*>(x) + i*2;
    float4 f0 = xp[0], f1 = xp[1];
    uint4 hi;
    hi.x = pack_f16(f0.x, f0.y);
    hi.y = pack_f16(f0.z, f0.w);
    hi.z = pack_f16(f1.x, f1.y);
    hi.w = pack_f16(f1.z, f1.w);
    reinterpret_cast<uint4*>(g_xhi)[i] = hi;
}

// ---------------------------------------------------------------- GEMM (r14, best known)
__global__ __launch_bounds__(256, 2) void gemm_mma(const float* __restrict__ adj)
{
    extern __shared__ __align__(16) char smem[];
    u32* SU = reinterpret_cast<u32*>(smem);
    const u32 sb = smem_u32(smem);

    const int tid = threadIdx.x;
    const int wid = tid >> 5;
    const int lane = tid & 31;
    const int tig = lane & 3;
    const int g   = lane >> 2;
    const int wm  = wid >> 1;        // warp row 0..3 (32 rows each)
    const int wn  = wid & 1;         // warp col 0..1 (48 cols each)

    const int lrow = lane & 15;
    const int lk16 = (lane >> 4) * 4;   // 0 or 4 u32

    const int r0    = blockIdx.x * ROWS;
    const int split = blockIdx.y;
    const int k0    = split * KPER;

    const int arow = tid >> 1;
    const int ahalf = tid & 1;
    const float4* aprow = reinterpret_cast<const float4*>(
        &adj[(size_t)(r0 + arow)*NN + k0 + ahalf*16]);

    float4 a4[2][4];

#define LOADA(set, it) do { \
    const float4* ap_ = aprow + (it)*8; \
    _Pragma("unroll") for (int p=0;p<4;p++) a4[set][p] = ap_[p]; } while(0)

#define CPB(stage, it) do { \
    u32 bbase_ = sb + (stage)*ST_BYTES; \
    int ku_ = (k0 + (it)*KC) >> 1; \
    _Pragma("unroll") for (int q=0;q<2;q++){ \
        int idx_ = q*256 + tid; \
        if (idx_ < 384){ \
            int n_ = idx_ >> 2, j4_ = idx_ & 3; \
            const u32* src_ = g_xhi + (size_t)n_*2048 + ku_ + j4_*4; \
            u32 dst_ = bbase_ + (U_BH + n_*20 + j4_*4)*4; \
            cpasync16(dst_, src_); } } } while(0)

#define STSA(stage, set) do { \
    u32* st_ = SU + (stage)*ST_U32; \
    uint4 hv0_, hv1_; \
    hv0_.x = pack_f16(a4[set][0].x, a4[set][0].y); \
    hv0_.y = pack_f16(a4[set][0].z, a4[set][0].w); \
    hv0_.z = pack_f16(a4[set][1].x, a4[set][1].y); \
    hv0_.w = pack_f16(a4[set][1].z, a4[set][1].w); \
    hv1_.x = pack_f16(a4[set][2].x, a4[set][2].y); \
    hv1_.y = pack_f16(a4[set][2].z, a4[set][2].w); \
    hv1_.z = pack_f16(a4[set][3].x, a4[set][3].y); \
    hv1_.w = pack_f16(a4[set][3].z, a4[set][3].w); \
    int o_ = arow*20 + ahalf*8; \
    *reinterpret_cast<uint4*>(st_ + U_AH + o_    ) = hv0_; \
    *reinterpret_cast<uint4*>(st_ + U_AH + o_ + 4) = hv1_; } while(0)

    float acc[2][6][4];
    #pragma unroll
    for (int mt=0;mt<2;mt++)
        #pragma unroll
        for (int nt=0;nt<6;nt++)
            #pragma unroll
            for (int c=0;c<4;c++) acc[mt][nt][c] = 0.f;

    LOADA(0, 0);
    CPB(0, 0); cp_commit();
    LOADA(1, 1);
    STSA(0, 0);
    cp_wait0();
    __syncthreads();

    for (int it = 0; it < NITS; it++){
        const int s = it & 1;
        if (it + 1 < NITS){
            CPB(s^1, it+1); cp_commit();
            STSA(s^1, (it+1)&1);
        }
        if (it + 2 < NITS) LOADA(s, it+2);

        const u32 stb = sb + s*ST_BYTES;
        #pragma unroll
        for (int kst = 0; kst < 2; kst++){
            const u32 koff = (u32)(kst*8 + lk16);
            u32 ah[2][4];
            #pragma unroll
            for (int mt=0;mt<2;mt++){
                u32 ad = stb + ((u32)((wm*32 + mt*16 + lrow)*20) + koff)*4;
                ldsm4(ah[mt], ad);
            }
            // B x4: r0=(n0-7,k0-7), r1=(n8-15,k0-7), r2=(n0-7,k8-15), r3=(n8-15,k8-15)
            u32 bh[6][2];
            #pragma unroll
            for (int p=0;p<3;p++){
                u32 bd = stb + ((u32)((wn*48 + p*16 + lrow)*20) + koff)*4;
                u32 r[4];
                ldsm4(r, bd + U_BH*4);
                bh[2*p][0]=r[0]; bh[2*p][1]=r[2]; bh[2*p+1][0]=r[1]; bh[2*p+1][1]=r[3];
            }
            #pragma unroll
            for (int mt=0;mt<2;mt++)
                #pragma unroll
                for (int nt=0;nt<6;nt++)
                    mma16816(acc[mt][nt], ah[mt], bh[nt]);
        }

        if (it + 1 < NITS) cp_wait0();
        __syncthreads();
    }

    float* plane = g_part + (size_t)split * CN;
    #pragma unroll
    for (int mt=0;mt<2;mt++){
        #pragma unroll
        for (int nt=0;nt<6;nt++){
            int cbase = wn*48 + nt*8 + tig*2;
            #pragma unroll
            for (int h=0;h<2;h++){
                int r = r0 + wm*32 + mt*16 + g + h*8;
                int k = r >> 12, n = r & (NN-1);
                #pragma unroll
                for (int cc=0;cc<2;cc++){
                    int col = cbase + cc;
                    int b = col / TT, t = col - b*TT;
                    plane[(((size_t)(k*BB + b)*TT + t) << 12) + n] = acc[mt][nt][h*2+cc];
                }
            }
        }
    }
}

// ---------------------------------------------------------------- reduce
__global__ __launch_bounds__(256) void reduce_C(){
    int i = blockIdx.x*256 + threadIdx.x;            // float4 index, CN/4 total
    const float4* gp = reinterpret_cast<const float4*>(g_part);
    float4 s = gp[i];
    #pragma unroll
    for (int p=1;p<SPLITK;p++){
        float4 v = gp[(size_t)p*(CN/4) + i];
        s.x += v.x; s.y += v.y; s.z += v.z; s.w += v.w;
    }
    reinterpret_cast<float4*>(g_C)[i] = s;
}

// ---------------------------------------------------------------- epilogue
// Same per-warp structure as r12 (16 bn/warp, 2n/thread, padded gws), but
// 128-thread CTAs x 512 grid -> no grid-limited occupancy, single wave.
__global__ __launch_bounds__(128) void epilogue_kernel(
    const float* __restrict__ x,
    const float* __restrict__ cheb_w,
    const float* __restrict__ gcn_w,
    const float* __restrict__ gcn_b,
    const float* __restrict__ glu1_w,
    const float* __restrict__ glu1_b,
    const float* __restrict__ glu2_w,
    const float* __restrict__ glu2_b,
    float* __restrict__ out)
{
    __shared__ __align__(16) float gws[TT*GSTRIDE];    // [t][j*12+o], padded rows
    __shared__ float cws[HIDD*3];
    __shared__ float w1s[FOUT*6*3], w2s[FOUT*6*3];
    __shared__ float gbs[FOUT], b1s[FOUT], b2s[FOUT];

    const int tid = threadIdx.x;
    for (int i=tid; i<TT*HIDD*FOUT; i+=128){
        int o = i % FOUT; int tj = i / FOUT; int t = tj >> 6; int j = tj & 63;
        gws[t*GSTRIDE + j*FOUT + o] = gcn_w[(o*TT + t)*HIDD + j];
    }
    for (int i=tid; i<HIDD*3; i+=128) cws[i] = cheb_w[i];
    for (int i=tid; i<FOUT*18; i+=128){
        int kh = i % 3; int oc = i / 3;
        w1s[i] = glu1_w[(oc*3 + kh)*3 + 1];   // only kw=1 contributes (W==1)
        w2s[i] = glu2_w[(oc*3 + kh)*3 + 1];
    }
    if (tid < FOUT){ gbs[tid]=gcn_b[tid]; b1s[tid]=glu1_b[tid]; b2s[tid]=glu2_b[tid]; }
    __syncthreads();

    const int lane = tid & 31;
    const int h    = lane >> 3;                 // quarter: t in [3h, 3h+3)
    const int gw   = blockIdx.x*4 + (tid >> 5); // global warp id
    const int bn0  = gw*16 + (lane & 7);
    const int b    = bn0 >> 12;
    const int n0   = bn0 & (NN-1);

    float y0[3][3], y1[3][3];
    #pragma unroll
    for (int k=0;k<3;k++)
        #pragma unroll
        for (int lt=0;lt<3;lt++){
            size_t off = (((size_t)(k*BB + b)*TT + (h*3+lt)) << 12) + n0;
            y0[lt][k] = g_C[off];
            y1[lt][k] = g_C[off + 8];
        }

    ull acc0[6], acc1[6];
    #pragma unroll
    for (int j=0;j<6;j++){ acc0[j] = 0ull; acc1[j] = 0ull; }

    #pragma unroll
    for (int lt=0;lt<3;lt++){
        const float* gbase = &gws[(h*3+lt)*GSTRIDE];
        #pragma unroll 8
        for (int j=0;j<HIDD;j++){
            float w0 = cws[j*3], w1 = cws[j*3+1], w2 = cws[j*3+2];
            float c0 = fmaxf(y0[lt][0]*w0 + y0[lt][1]*w1 + y0[lt][2]*w2, 0.f);
            float c1 = fmaxf(y1[lt][0]*w0 + y1[lt][1]*w1 + y1[lt][2]*w2, 0.f);
            ull cd0 = f2dup(c0), cd1 = f2dup(c1);
            const float* gp = gbase + j*FOUT;
            ulonglong2 g0 = *reinterpret_cast<const ulonglong2*>(gp);
            ulonglong2 g1 = *reinterpret_cast<const ulonglong2*>(gp+4);
            ulonglong2 g2 = *reinterpret_cast<const ulonglong2*>(gp+8);
            ffma2(acc0[0], cd0, g0.x); ffma2(acc0[1], cd0, g0.y);
            ffma2(acc0[2], cd0, g1.x); ffma2(acc0[3], cd0, g1.y);
            ffma2(acc0[4], cd0, g2.x); ffma2(acc0[5], cd0, g2.y);
            ffma2(acc1[0], cd1, g0.x); ffma2(acc1[1], cd1, g0.y);
            ffma2(acc1[2], cd1, g1.x); ffma2(acc1[3], cd1, g1.y);
            ffma2(acc1[4], cd1, g2.x); ffma2(acc1[5], cd1, g2.y);
        }
    }

    const ull ONE = f2dup(1.0f);
    #pragma unroll
    for (int j=0;j<6;j++){
        ull v;
        v = __shfl_xor_sync(0xFFFFFFFFu, acc0[j], 8);  ffma2(acc0[j], v, ONE);
        v = __shfl_xor_sync(0xFFFFFFFFu, acc0[j], 16); ffma2(acc0[j], v, ONE);
        v = __shfl_xor_sync(0xFFFFFFFFu, acc1[j], 8);  ffma2(acc1[j], v, ONE);
        v = __shfl_xor_sync(0xFFFFFFFFu, acc1[j], 16); ffma2(acc1[j], v, ONE);
    }

    const int uses_v = h & 1;
    const int second = h >> 1;
    const int myn    = n0 + second*8;
    const float* ws = uses_v ? w2s : w1s;
    const float* bs = uses_v ? b2s : b1s;
    float xr[6][3];
    #pragma unroll
    for (int c=0;c<6;c++){
        #pragma unroll
        for (int kh=0;kh<3;kh++){
            int pos = myn + 2*kh - 2;
            bool ok = (pos >= 0) && (pos < NN);
            xr[c][kh] = ok ? x[((size_t)b*TT + uses_v*6 + c)*NN + pos] : 0.f;
        }
    }
    float val[FOUT];
    #pragma unroll
    for (int o=0;o<FOUT;o++){
        float v = bs[o];
        #pragma unroll
        for (int c=0;c<6;c++)
            #pragma unroll
            for (int kh=0;kh<3;kh++)
                v += ws[(o*6+c)*3+kh]*xr[c][kh];
        val[o] = v;
    }
    float pv[FOUT];
    #pragma unroll
    for (int o=0;o<FOUT;o++)
        pv[o] = __shfl_xor_sync(0xFFFFFFFFu, val[o], 8);

    if (!uses_v){
        const ull* acc = second ? acc1 : acc0;
        #pragma unroll
        for (int o=0;o<FOUT;o++){
            float sg = 1.f/(1.f + __expf(-pv[o]));
            union { ull u; float f[2]; } vv; vv.u = acc[o>>1];
            float sgc = vv.f[o&1] + gbs[o];
            out[((size_t)b*FOUT + o)*NN + myn] = val[o]*sg + sgc;
        }
    }
}

// ----------------------------------------------------------------
extern "C" void kernel_launch(void* const* d_in, const int* in_sizes, int n_in,
                              void* d_out, int out_size)
{
    (void)in_sizes; (void)n_in; (void)out_size;
    const float* x      = (const float*)d_in[0];
    const float* adj    = (const float*)d_in[1];
    const float* cheb_w = (const float*)d_in[2];
    const float* gcn_w  = (const float*)d_in[3];
    const float* gcn_b  = (const float*)d_in[4];
    const float* glu1_w = (const float*)d_in[5];
    const float* glu1_b = (const float*)d_in[6];
    const float* glu2_w = (const float*)d_in[7];
    const float* glu2_b = (const float*)d_in[8];
    float* out = (float*)d_out;

    split_x<<<(BT*NN/8)/256, 256>>>(x);

    cudaFuncSetAttribute(gemm_mma,
                         cudaFuncAttributeMaxDynamicSharedMemorySize, SMEM_TOTAL);
    gemm_mma<<<dim3(RTILES, SPLITK), 256, SMEM_TOTAL>>>(adj);

    reduce_C<<<(CN/4)/256, 256>>>();

    // 64 bn per CTA (4 warps x 16 bn) -> 512 CTAs, single wave
    epilogue_kernel<<<(BB*NN)/64, 128>>>(x, cheb_w, gcn_w, gcn_b,
                                         glu1_w, glu1_b, glu2_w, glu2_b, out);
}

// round 16
// speedup vs baseline: 1.1928x; 1.1928x over previous
#include <cuda_runtime.h>
#include <cuda_fp16.h>
#include <cstdint>

typedef unsigned long long ull;
typedef unsigned int u32;

#define NN    4096
#define BB    8
#define TT    12
#define BT    96
#define FOUT  12
#define HIDD  64
#define ROWS  128          // M tile
#define KC    32           // K chunk
#define SPLITK 3           // unequal chunks: 43,43,42 k-iters -> 288 CTAs = 1 wave
#define RTILES (3*NN/ROWS) // 96
#define GSTRIDE 776        // gws row stride (768 + 8 pad: kills 4-way t-bank conflict)

#define CN (3*BB*TT*NN)    // 1,179,648

// stage layout in u32 units (pitch 20 u32 per row -> conflict-free LDS/LDSM)
#define U_AH 0
#define U_BH (128*20)                 // 2560
#define ST_U32 (128*20 + 96*20)       // 4480
#define ST_BYTES (ST_U32*4)           // 17920
#define SMEM_TOTAL (2*ST_BYTES)       // 35840

__device__ float g_part[SPLITK * CN];          // 14.2 MB partial planes
__device__ float g_C[CN];                      // reduced C, [k][b][t][n]
__device__ __align__(16) u32 g_xhi[BT*NN/2];   // x fp16 pairs

// ---------------------------------------------------------------- helpers
__device__ __forceinline__ u32 smem_u32(const void* p){
    u32 a; asm("{ .reg .u64 t; cvta.to.shared.u64 t, %1; cvt.u32.u64 %0, t; }"
               : "=r"(a) : "l"(p));
    return a;
}
__device__ __forceinline__ void cpasync16(u32 dst, const void* src){
    asm volatile("cp.async.cg.shared.global [%0], [%1], 16;"
                 :: "r"(dst), "l"(src) : "memory");
}
__device__ __forceinline__ void cp_commit(){
    asm volatile("cp.async.commit_group;" ::: "memory");
}
__device__ __forceinline__ void cp_wait0(){
    asm volatile("cp.async.wait_group 0;" ::: "memory");
}
__device__ __forceinline__ void ldsm4(u32* r, u32 addr){
    asm volatile("ldmatrix.sync.aligned.m8n8.x4.shared.b16 {%0,%1,%2,%3}, [%4];"
                 : "=r"(r[0]), "=r"(r[1]), "=r"(r[2]), "=r"(r[3]) : "r"(addr));
}
// pack two floats to one fp16x2 (rn)
__device__ __forceinline__ u32 pack_f16(float f0, float f1){
    u32 r; asm("cvt.rn.f16x2.f32 %0, %1, %2;" : "=r"(r) : "f"(f1), "f"(f0));
    return r;
}
__device__ __forceinline__ void mma16816(float* c, const u32* a, const u32* b){
    asm volatile(
      "mma.sync.aligned.m16n8k16.row.col.f32.f16.f16.f32 "
      "{%0,%1,%2,%3}, {%4,%5,%6,%7}, {%8,%9}, {%0,%1,%2,%3};"
      : "+f"(c[0]), "+f"(c[1]), "+f"(c[2]), "+f"(c[3])
      : "r"(a[0]), "r"(a[1]), "r"(a[2]), "r"(a[3]), "r"(b[0]), "r"(b[1]));
}
__device__ __forceinline__ ull f2dup(float f){
    ull r; asm("mov.b64 %0, {%1, %1};" : "=l"(r) : "f"(f)); return r;
}
__device__ __forceinline__ void ffma2(ull &d, ull a, ull b){
    asm("fma.rn.f32x2 %0, %1, %2, %3;" : "=l"(d) : "l"(a), "l"(b), "l"(d));
}

// ---------------------------------------------------------------- split x
__global__ __launch_bounds__(256) void split_x(const float* __restrict__ x){
    int i = blockIdx.x*256 + threadIdx.x;        // group of 4 pairs
    const float4* xp = reinterpret_cast<const float4*>(x) + i*2;
    float4 f0 = xp[0], f1 = xp[1];
    uint4 hi;
    hi.x = pack_f16(f0.x, f0.y);
    hi.y = pack_f16(f0.z, f0.w);
    hi.z = pack_f16(f1.x, f1.y);
    hi.w = pack_f16(f1.z, f1.w);
    reinterpret_cast<uint4*>(g_xhi)[i] = hi;
}

// ---------------------------------------------------------------- GEMM
// 1-term fp16, unequal split-K: split s covers k-iters [43s, 43s+nits),
// nits = 43,43,42. 288 CTAs at 2/SM -> exactly one wave.
__global__ __launch_bounds__(256, 2) void gemm_mma(const float* __restrict__ adj)
{
    extern __shared__ __align__(16) char smem[];
    u32* SU = reinterpret_cast<u32*>(smem);
    const u32 sb = smem_u32(smem);

    const int tid = threadIdx.x;
    const int wid = tid >> 5;
    const int lane = tid & 31;
    const int tig = lane & 3;
    const int g   = lane >> 2;
    const int wm  = wid >> 1;        // warp row 0..3 (32 rows each)
    const int wn  = wid & 1;         // warp col 0..1 (48 cols each)

    const int lrow = lane & 15;
    const int lk16 = (lane >> 4) * 4;   // 0 or 4 u32

    const int r0    = blockIdx.x * ROWS;
    const int split = blockIdx.y;
    const int nits  = (split == 2) ? 42 : 43;
    const int k0    = split * 43 * KC;

    const int arow = tid >> 1;
    const int ahalf = tid & 1;
    const float4* aprow = reinterpret_cast<const float4*>(
        &adj[(size_t)(r0 + arow)*NN + k0 + ahalf*16]);

    float4 a4[2][4];

#define LOADA(set, it) do { \
    const float4* ap_ = aprow + (it)*8; \
    _Pragma("unroll") for (int p=0;p<4;p++) a4[set][p] = ap_[p]; } while(0)

#define CPB(stage, it) do { \
    u32 bbase_ = sb + (stage)*ST_BYTES; \
    int ku_ = (k0 + (it)*KC) >> 1; \
    _Pragma("unroll") for (int q=0;q<2;q++){ \
        int idx_ = q*256 + tid; \
        if (idx_ < 384){ \
            int n_ = idx_ >> 2, j4_ = idx_ & 3; \
            const u32* src_ = g_xhi + (size_t)n_*2048 + ku_ + j4_*4; \
            u32 dst_ = bbase_ + (U_BH + n_*20 + j4_*4)*4; \
            cpasync16(dst_, src_); } } } while(0)

#define STSA(stage, set) do { \
    u32* st_ = SU + (stage)*ST_U32; \
    uint4 hv0_, hv1_; \
    hv0_.x = pack_f16(a4[set][0].x, a4[set][0].y); \
    hv0_.y = pack_f16(a4[set][0].z, a4[set][0].w); \
    hv0_.z = pack_f16(a4[set][1].x, a4[set][1].y); \
    hv0_.w = pack_f16(a4[set][1].z, a4[set][1].w); \
    hv1_.x = pack_f16(a4[set][2].x, a4[set][2].y); \
    hv1_.y = pack_f16(a4[set][2].z, a4[set][2].w); \
    hv1_.z = pack_f16(a4[set][3].x, a4[set][3].y); \
    hv1_.w = pack_f16(a4[set][3].z, a4[set][3].w); \
    int o_ = arow*20 + ahalf*8; \
    *reinterpret_cast<uint4*>(st_ + U_AH + o_    ) = hv0_; \
    *reinterpret_cast<uint4*>(st_ + U_AH + o_ + 4) = hv1_; } while(0)

    float acc[2][6][4];
    #pragma unroll
    for (int mt=0;mt<2;mt++)
        #pragma unroll
        for (int nt=0;nt<6;nt++)
            #pragma unroll
            for (int c=0;c<4;c++) acc[mt][nt][c] = 0.f;

    LOADA(0, 0);
    CPB(0, 0); cp_commit();
    LOADA(1, 1);
    STSA(0, 0);
    cp_wait0();
    __syncthreads();

    for (int it = 0; it < nits; it++){
        const int s = it & 1;
        if (it + 1 < nits){
            CPB(s^1, it+1); cp_commit();
            STSA(s^1, (it+1)&1);
        }
        if (it + 2 < nits) LOADA(s, it+2);

        const u32 stb = sb + s*ST_BYTES;
        #pragma unroll
        for (int kst = 0; kst < 2; kst++){
            const u32 koff = (u32)(kst*8 + lk16);
            u32 ah[2][4];
            #pragma unroll
            for (int mt=0;mt<2;mt++){
                u32 ad = stb + ((u32)((wm*32 + mt*16 + lrow)*20) + koff)*4;
                ldsm4(ah[mt], ad);
            }
            // B x4: r0=(n0-7,k0-7), r1=(n8-15,k0-7), r2=(n0-7,k8-15), r3=(n8-15,k8-15)
            u32 bh[6][2];
            #pragma unroll
            for (int p=0;p<3;p++){
                u32 bd = stb + ((u32)((wn*48 + p*16 + lrow)*20) + koff)*4;
                u32 r[4];
                ldsm4(r, bd + U_BH*4);
                bh[2*p][0]=r[0]; bh[2*p][1]=r[2]; bh[2*p+1][0]=r[1]; bh[2*p+1][1]=r[3];
            }
            #pragma unroll
            for (int mt=0;mt<2;mt++)
                #pragma unroll
                for (int nt=0;nt<6;nt++)
                    mma16816(acc[mt][nt], ah[mt], bh[nt]);
        }

        if (it + 1 < nits) cp_wait0();
        __syncthreads();
    }

    float* plane = g_part + (size_t)split * CN;
    #pragma unroll
    for (int mt=0;mt<2;mt++){
        #pragma unroll
        for (int nt=0;nt<6;nt++){
            int cbase = wn*48 + nt*8 + tig*2;
            #pragma unroll
            for (int h=0;h<2;h++){
                int r = r0 + wm*32 + mt*16 + g + h*8;
                int k = r >> 12, n = r & (NN-1);
                #pragma unroll
                for (int cc=0;cc<2;cc++){
                    int col = cbase + cc;
                    int b = col / TT, t = col - b*TT;
                    plane[(((size_t)(k*BB + b)*TT + t) << 12) + n] = acc[mt][nt][h*2+cc];
                }
            }
        }
    }
}

// ---------------------------------------------------------------- reduce
__global__ __launch_bounds__(256) void reduce_C(){
    int i = blockIdx.x*256 + threadIdx.x;            // float4 index, CN/4 total
    const float4* gp = reinterpret_cast<const float4*>(g_part);
    float4 s = gp[i];
    #pragma unroll
    for (int p=1;p<SPLITK;p++){
        float4 v = gp[(size_t)p*(CN/4) + i];
        s.x += v.x; s.y += v.y; s.z += v.z; s.w += v.w;
    }
    reinterpret_cast<float4*>(g_C)[i] = s;
}

// ---------------------------------------------------------------- epilogue (r14/r12, best known: 256 thr, grid 256)
__global__ __launch_bounds__(256) void epilogue_kernel(
    const float* __restrict__ x,
    const float* __restrict__ cheb_w,
    const float* __restrict__ gcn_w,
    const float* __restrict__ gcn_b,
    const float* __restrict__ glu1_w,
    const float* __restrict__ glu1_b,
    const float* __restrict__ glu2_w,
    const float* __restrict__ glu2_b,
    float* __restrict__ out)
{
    __shared__ __align__(16) float gws[TT*GSTRIDE];    // [t][j*12+o], padded rows
    __shared__ float cws[HIDD*3];
    __shared__ float w1s[FOUT*6*3], w2s[FOUT*6*3];
    __shared__ float gbs[FOUT], b1s[FOUT], b2s[FOUT];

    const int tid = threadIdx.x;
    for (int i=tid; i<TT*HIDD*FOUT; i+=256){
        int o = i % FOUT; int tj = i / FOUT; int t = tj >> 6; int j = tj & 63;
        gws[t*GSTRIDE + j*FOUT + o] = gcn_w[(o*TT + t)*HIDD + j];
    }
    for (int i=tid; i<HIDD*3; i+=256) cws[i] = cheb_w[i];
    for (int i=tid; i<FOUT*18; i+=256){
        int kh = i % 3; int oc = i / 3;
        w1s[i] = glu1_w[(oc*3 + kh)*3 + 1];   // only kw=1 contributes (W==1)
        w2s[i] = glu2_w[(oc*3 + kh)*3 + 1];
    }
    if (tid < FOUT){ gbs[tid]=gcn_b[tid]; b1s[tid]=glu1_b[tid]; b2s[tid]=glu2_b[tid]; }
    __syncthreads();

    const int lane = tid & 31;
    const int h    = lane >> 3;                 // quarter: t in [3h, 3h+3)
    const int gw   = blockIdx.x*8 + (tid >> 5); // global warp id
    const int bn0  = gw*16 + (lane & 7);
    const int b    = bn0 >> 12;
    const int n0   = bn0 & (NN-1);

    float y0[3][3], y1[3][3];
    #pragma unroll
    for (int k=0;k<3;k++)
        #pragma unroll
        for (int lt=0;lt<3;lt++){
            size_t off = (((size_t)(k*BB + b)*TT + (h*3+lt)) << 12) + n0;
            y0[lt][k] = g_C[off];
            y1[lt][k] = g_C[off + 8];
        }

    ull acc0[6], acc1[6];
    #pragma unroll
    for (int j=0;j<6;j++){ acc0[j] = 0ull; acc1[j] = 0ull; }

    #pragma unroll
    for (int lt=0;lt<3;lt++){
        const float* gbase = &gws[(h*3+lt)*GSTRIDE];
        #pragma unroll 8
        for (int j=0;j<HIDD;j++){
            float w0 = cws[j*3], w1 = cws[j*3+1], w2 = cws[j*3+2];
            float c0 = fmaxf(y0[lt][0]*w0 + y0[lt][1]*w1 + y0[lt][2]*w2, 0.f);
            float c1 = fmaxf(y1[lt][0]*w0 + y1[lt][1]*w1 + y1[lt][2]*w2, 0.f);
            ull cd0 = f2dup(c0), cd1 = f2dup(c1);
            const float* gp = gbase + j*FOUT;
            ulonglong2 g0 = *reinterpret_cast<const ulonglong2*>(gp);
            ulonglong2 g1 = *reinterpret_cast<const ulonglong2*>(gp+4);
            ulonglong2 g2 = *reinterpret_cast<const ulonglong2*>(gp+8);
            ffma2(acc0[0], cd0, g0.x); ffma2(acc0[1], cd0, g0.y);
            ffma2(acc0[2], cd0, g1.x); ffma2(acc0[3], cd0, g1.y);
            ffma2(acc0[4], cd0, g2.x); ffma2(acc0[5], cd0, g2.y);
            ffma2(acc1[0], cd1, g0.x); ffma2(acc1[1], cd1, g0.y);
            ffma2(acc1[2], cd1, g1.x); ffma2(acc1[3], cd1, g1.y);
            ffma2(acc1[4], cd1, g2.x); ffma2(acc1[5], cd1, g2.y);
        }
    }

    const ull ONE = f2dup(1.0f);
    #pragma unroll
    for (int j=0;j<6;j++){
        ull v;
        v = __shfl_xor_sync(0xFFFFFFFFu, acc0[j], 8);  ffma2(acc0[j], v, ONE);
        v = __shfl_xor_sync(0xFFFFFFFFu, acc0[j], 16); ffma2(acc0[j], v, ONE);
        v = __shfl_xor_sync(0xFFFFFFFFu, acc1[j], 8);  ffma2(acc1[j], v, ONE);
        v = __shfl_xor_sync(0xFFFFFFFFu, acc1[j], 16); ffma2(acc1[j], v, ONE);
    }

    const int uses_v = h & 1;
    const int second = h >> 1;
    const int myn    = n0 + second*8;
    const float* ws = uses_v ? w2s : w1s;
    const float* bs = uses_v ? b2s : b1s;
    float xr[6][3];
    #pragma unroll
    for (int c=0;c<6;c++){
        #pragma unroll
        for (int kh=0;kh<3;kh++){
            int pos = myn + 2*kh - 2;
            bool ok = (pos >= 0) && (pos < NN);
            xr[c][kh] = ok ? x[((size_t)b*TT + uses_v*6 + c)*NN + pos] : 0.f;
        }
    }
    float val[FOUT];
    #pragma unroll
    for (int o=0;o<FOUT;o++){
        float v = bs[o];
        #pragma unroll
        for (int c=0;c<6;c++)
            #pragma unroll
            for (int kh=0;kh<3;kh++)
                v += ws[(o*6+c)*3+kh]*xr[c][kh];
        val[o] = v;
    }
    float pv[FOUT];
    #pragma unroll
    for (int o=0;o<FOUT;o++)
        pv[o] = __shfl_xor_sync(0xFFFFFFFFu, val[o], 8);

    if (!uses_v){
        const ull* acc = second ? acc1 : acc0;
        #pragma unroll
        for (int o=0;o<FOUT;o++){
            float sg = 1.f/(1.f + __expf(-pv[o]));
            union { ull u; float f[2]; } vv; vv.u = acc[o>>1];
            float sgc = vv.f[o&1] + gbs[o];
            out[((size_t)b*FOUT + o)*NN + myn] = val[o]*sg + sgc;
        }
    }
}

// ----------------------------------------------------------------
extern "C" void kernel_launch(void* const* d_in, const int* in_sizes, int n_in,
                              void* d_out, int out_size)
{
    (void)in_sizes; (void)n_in; (void)out_size;
    const float* x      = (const float*)d_in[0];
    const float* adj    = (const float*)d_in[1];
    const float* cheb_w = (const float*)d_in[2];
    const float* gcn_w  = (const float*)d_in[3];
    const float* gcn_b  = (const float*)d_in[4];
    const float* glu1_w = (const float*)d_in[5];
    const float* glu1_b = (const float*)d_in[6];
    const float* glu2_w = (const float*)d_in[7];
    const float* glu2_b = (const float*)d_in[8];
    float* out = (float*)d_out;

    split_x<<<(BT*NN/8)/256, 256>>>(x);

    cudaFuncSetAttribute(gemm_mma,
                         cudaFuncAttributeMaxDynamicSharedMemorySize, SMEM_TOTAL);
    gemm_mma<<<dim3(RTILES, SPLITK), 256, SMEM_TOTAL>>>(adj);

    reduce_C<<<(CN/4)/256, 256>>>();

    epilogue_kernel<<<(BB*NN)/128, 256>>>(x, cheb_w, gcn_w, gcn_b,
                                          glu1_w, glu1_b, glu2_w, glu2_b, out);
}